// round 10
// baseline (speedup 1.0000x reference)
#include <cuda_runtime.h>
#include <cuda.h>
#include <dlfcn.h>
#include <cstdint>

// GateRecurrent2dnoind: H[h,w] = B*X + G1*H[h-1,w-1] + G2*H[h,w-1] + G3*H[h+1,w-1]
// [16, 32, 128, 128] fp32.
// Row-pair packed view: plane = 64 "rows" x 256 floats (new-row r = physical
// rows 2r,2r+1). TMA box [32,64] + SW128 -> all segments are full 128B lines.
// Persistent CTA owns 4 planes (grid 128, 1 CTA/SM, 192KB smem). Thread 0:
// TMA producer, depth-2 ring of 32-col stages (5 tensors x (even,odd) boxes).
// Warp 1: consumer; lane l owns rows {2l, 2l+1, 2l+64, 2l+65} -> adjacent-row
// coupling is lane-local, only 4 shfls per column. Output in packed layout,
// double-buffered, flushed as full-line TMA stores with deferred waits.

#define HH       128
#define NPL      4                    // planes per CTA
#define NSP      4                    // stages (32-col tiles) per plane
#define NTS      (NPL * NSP)          // 16 stages per CTA
#define DEPTH    2
#define HALF_F   2048                 // 64 rows x 32 floats (one parity box)
#define SLOT_F   4096                 // even+odd halves per tensor per stage
#define STAGE_F  (5 * SLOT_F)         // 20480 floats = 80KB
#define IN_F     (DEPTH * STAGE_F)    // 40960 floats = 160KB
#define OUTBUF_F 4096                 // one packed 32-col out tile
#define SM_F     (IN_F + 2 * OUTBUF_F)
#define BAR_OFF  (SM_F * 4)           // 196608
#define SMEM_BYTES (BAR_OFF + 64)
#define STAGE_BYTES (STAGE_F * 4)     // 81920

#define FULLM 0xFFFFFFFFu
#define COMP(v, j) ((j) == 0 ? (v).x : (j) == 1 ? (v).y : (j) == 2 ? (v).z : (v).w)

// ---------------- PTX helpers ----------------
__device__ __forceinline__ void mbar_init(uint32_t a, uint32_t cnt) {
    asm volatile("mbarrier.init.shared.b64 [%0], %1;" :: "r"(a), "r"(cnt) : "memory");
}
__device__ __forceinline__ void mbar_expect_tx(uint32_t a, uint32_t bytes) {
    asm volatile("mbarrier.arrive.expect_tx.shared.b64 _, [%0], %1;"
                 :: "r"(a), "r"(bytes) : "memory");
}
__device__ __forceinline__ void mbar_arrive(uint32_t a) {
    asm volatile("mbarrier.arrive.shared.b64 _, [%0];" :: "r"(a) : "memory");
}
__device__ __forceinline__ void mbar_wait_acq(uint32_t a, uint32_t ph) {
    asm volatile(
        "{\n\t.reg .pred P;\n"
        "W%=:\n\t"
        "mbarrier.try_wait.parity.acquire.cta.shared::cta.b64 P, [%0], %1, 0x989680;\n\t"
        "@P bra D%=;\n\t"
        "bra W%=;\n"
        "D%=:\n\t}"
        :: "r"(a), "r"(ph) : "memory");
}
__device__ __forceinline__ void mbar_wait_rlx(uint32_t a, uint32_t ph) {
    asm volatile(
        "{\n\t.reg .pred P;\n"
        "W%=:\n\t"
        "mbarrier.try_wait.parity.relaxed.cta.shared::cta.b64 P, [%0], %1, 0x989680;\n\t"
        "@P bra D%=;\n\t"
        "bra W%=;\n"
        "D%=:\n\t}"
        :: "r"(a), "r"(ph) : "memory");
}
__device__ __forceinline__ void tma_ld2d(uint32_t smem, const void* map,
                                         int32_t cx, int32_t cy, uint32_t mbar) {
    asm volatile(
        "cp.async.bulk.tensor.2d.shared::cta.global.tile.mbarrier::complete_tx::bytes "
        "[%0], [%1, {%2, %3}], [%4];"
        :: "r"(smem), "l"(map), "r"(cx), "r"(cy), "r"(mbar) : "memory");
}
__device__ __forceinline__ void tma_st2d(const void* map, int32_t cx, int32_t cy,
                                         uint32_t smem) {
    asm volatile(
        "cp.async.bulk.tensor.2d.global.shared::cta.tile.bulk_group "
        "[%0, {%1, %2}], [%3];"
        :: "l"(map), "r"(cx), "r"(cy), "r"(smem) : "memory");
}
__device__ __forceinline__ void tma_st_commit() {
    asm volatile("cp.async.bulk.commit_group;" ::: "memory");
}
__device__ __forceinline__ void tma_st_wait1() {
    asm volatile("cp.async.bulk.wait_group 1;" ::: "memory");
}
__device__ __forceinline__ void tma_st_wait0() {
    asm volatile("cp.async.bulk.wait_group 0;" ::: "memory");
}
__device__ __forceinline__ void fence_async_shared() {
    asm volatile("fence.proxy.async.shared::cta;" ::: "memory");
}

// ---------------- kernel ----------------
__global__ __launch_bounds__(64, 1)
void gaterec2d_pk_kernel(const __grid_constant__ CUtensorMap mX,
                         const __grid_constant__ CUtensorMap mB,
                         const __grid_constant__ CUtensorMap m1,
                         const __grid_constant__ CUtensorMap m2,
                         const __grid_constant__ CUtensorMap m3,
                         const __grid_constant__ CUtensorMap mO)
{
    extern __shared__ float smf[];
    const uint32_t sb = (uint32_t)__cvta_generic_to_shared(smf);
    const int tid = threadIdx.x;
    const int plane0 = blockIdx.x * NPL;

    const uint32_t fullb  = sb + BAR_OFF;        // full[s]  at +8*s
    const uint32_t emptyb = sb + BAR_OFF + 16;   // empty[s] at +8*s

    if (tid == 0) {
        #pragma unroll
        for (int s = 0; s < DEPTH; ++s) {
            mbar_init(fullb  + 8u * s, 1);
            mbar_init(emptyb + 8u * s, 1);
        }
    }
    __syncthreads();

    if (tid == 0) {
        // ---------------- producer: seamless ring across 4 planes ----------------
        #pragma unroll 1
        for (int ts = 0; ts < NTS; ++ts) {
            const int s = ts & 1, k = ts >> 1;
            const int p = ts >> 2;               // plane within CTA
            const int t = ts & 3;                // 32-col tile within plane
            mbar_wait_rlx(emptyb + 8u * s, (uint32_t)((k & 1) ^ 1));
            mbar_expect_tx(fullb + 8u * s, STAGE_BYTES);
            const uint32_t slot = sb + (uint32_t)(s * STAGE_F) * 4u;
            const int cy  = (plane0 + p) * 64;   // packed-row base of this plane
            const int cxe = 32 * t;              // even-h cols
            const int cxo = 128 + 32 * t;        // odd-h cols
            #pragma unroll
            for (int i = 0; i < 5; ++i) {
                const void* mp = (i == 0) ? (const void*)&mX :
                                 (i == 1) ? (const void*)&mB :
                                 (i == 2) ? (const void*)&m1 :
                                 (i == 3) ? (const void*)&m2 : (const void*)&m3;
                const uint32_t tbase = slot + (uint32_t)(i * SLOT_F) * 4u;
                tma_ld2d(tbase,                      mp, cxe, cy, fullb + 8u * s);
                tma_ld2d(tbase + HALF_F * 4u,        mp, cxo, cy, fullb + 8u * s);
            }
        }
    } else if (tid >= 32) {
        // ---------------- consumer (warp 1) ----------------
        const int l   = tid & 31;
        const int lsw = l & 7;    // SW128 swizzle term, lane-constant (rows r=l, l+32)

        // state: s0=H[2l], s1=H[2l+1], s2=H[2l+64], s3=H[2l+65] (prev column)
        float s0v = 0.f, s1v = 0.f, s2v = 0.f, s3v = 0.f;

        #pragma unroll 1
        for (int ts = 0; ts < NTS; ++ts) {
            const int s = ts & 1, k = ts >> 1;
            const int p = ts >> 2;
            const int t = ts & 3;
            if (t == 0) { s0v = 0.f; s1v = 0.f; s2v = 0.f; s3v = 0.f; }

            mbar_wait_acq(fullb + 8u * s, (uint32_t)(k & 1));
            if (ts >= 2) { if (l == 0) tma_st_wait1(); }   // out buf reuse guard
            __syncwarp();

            const float* tb = smf + s * STAGE_F;
            float* sout = smf + IN_F + (ts & 1) * OUTBUF_F;

            // row offsets (floats) within a parity half: r*32
            const int rA = l * 32;          // r = l      (rows 2l / 2l+1)
            const int rB = (l + 32) * 32;   // r = l+32   (rows 2l+64 / 2l+65)

            #pragma unroll
            for (int g = 0; g < 8; ++g) {
                const int go = 4 * (g ^ lsw);   // swizzled 16B slot within 128B row

                // load 4 row-slots x 5 tensors (all conflict-free LDS.128)
                float4 xe0, xo0, xe2, xo2, be0, bo0, be2, bo2;
                float4 ae0[3], ao0[3], ae2[3], ao2[3];
                {
                    const float* tx = tb;
                    xe0 = *(const float4*)(tx + rA + go);
                    xo0 = *(const float4*)(tx + HALF_F + rA + go);
                    xe2 = *(const float4*)(tx + rB + go);
                    xo2 = *(const float4*)(tx + HALF_F + rB + go);
                    const float* tbb = tb + SLOT_F;
                    be0 = *(const float4*)(tbb + rA + go);
                    bo0 = *(const float4*)(tbb + HALF_F + rA + go);
                    be2 = *(const float4*)(tbb + rB + go);
                    bo2 = *(const float4*)(tbb + HALF_F + rB + go);
                    #pragma unroll
                    for (int i = 0; i < 3; ++i) {
                        const float* tg = tb + (2 + i) * SLOT_F;
                        ae0[i] = *(const float4*)(tg + rA + go);
                        ao0[i] = *(const float4*)(tg + HALF_F + rA + go);
                        ae2[i] = *(const float4*)(tg + rB + go);
                        ao2[i] = *(const float4*)(tg + HALF_F + rB + go);
                    }
                }

                float ov0[4], ov1[4], ov2[4], ov3[4];
                #pragma unroll
                for (int j = 0; j < 4; ++j) {
                    const float bx0 = COMP(be0, j) * COMP(xe0, j);
                    const float bx1 = COMP(bo0, j) * COMP(xo0, j);
                    const float bx2 = COMP(be2, j) * COMP(xe2, j);
                    const float bx3 = COMP(bo2, j) * COMP(xo2, j);

                    // 4 shfls: only cross-lane couplings
                    // u0 = H[2l-1] from lane l-1 s1; lane0 -> 0
                    const float u0 = __shfl_sync(FULLM, (l == 31) ? 0.f : s1v, (l + 31) & 31);
                    // d1 = H[2l+2] from lane l+1 s0; lane31 -> H[64] = s2 of lane0
                    const float d1 = __shfl_sync(FULLM, (l == 0) ? s2v : s0v, (l + 1) & 31);
                    // u2 = H[2l+63] from lane l-1 s3; lane0 -> H[63] = s1 of lane31
                    const float u2 = __shfl_sync(FULLM, (l == 31) ? s1v : s3v, (l + 31) & 31);
                    // d3 = H[2l+66] from lane l+1 s2; lane31 -> 0
                    const float d3 = __shfl_sync(FULLM, (l == 0) ? 0.f : s2v, (l + 1) & 31);

                    const float n0 = fmaf(COMP(ae0[0], j), u0,
                                     fmaf(COMP(ae0[1], j), s0v,
                                     fmaf(COMP(ae0[2], j), s1v, bx0)));
                    const float n1 = fmaf(COMP(ao0[0], j), s0v,
                                     fmaf(COMP(ao0[1], j), s1v,
                                     fmaf(COMP(ao0[2], j), d1, bx1)));
                    const float n2 = fmaf(COMP(ae2[0], j), u2,
                                     fmaf(COMP(ae2[1], j), s2v,
                                     fmaf(COMP(ae2[2], j), s3v, bx2)));
                    const float n3 = fmaf(COMP(ao2[0], j), s2v,
                                     fmaf(COMP(ao2[1], j), s3v,
                                     fmaf(COMP(ao2[2], j), d3, bx3)));

                    s0v = n0; s1v = n1; s2v = n2; s3v = n3;
                    ov0[j] = n0; ov1[j] = n1; ov2[j] = n2; ov3[j] = n3;
                }

                // store to packed out buffer (same layout as input boxes)
                float4 v0, v1, v2, v3;
                v0.x = ov0[0]; v0.y = ov0[1]; v0.z = ov0[2]; v0.w = ov0[3];
                v1.x = ov1[0]; v1.y = ov1[1]; v1.z = ov1[2]; v1.w = ov1[3];
                v2.x = ov2[0]; v2.y = ov2[1]; v2.z = ov2[2]; v2.w = ov2[3];
                v3.x = ov3[0]; v3.y = ov3[1]; v3.z = ov3[2]; v3.w = ov3[3];
                *(float4*)(sout + rA + go)          = v0;   // even, row l
                *(float4*)(sout + HALF_F + rA + go) = v1;   // odd,  row l
                *(float4*)(sout + rB + go)          = v2;   // even, row l+32
                *(float4*)(sout + HALF_F + rB + go) = v3;   // odd,  row l+32
            }

            __syncwarp();
            if (l == 0) {
                mbar_arrive(emptyb + 8u * s);   // stage consumed
                fence_async_shared();
                const int cy  = (plane0 + p) * 64;
                const uint32_t ob = sb + (uint32_t)(IN_F + (ts & 1) * OUTBUF_F) * 4u;
                tma_st2d(&mO, 32 * t, cy, ob);                       // even rows
                tma_st2d(&mO, 128 + 32 * t, cy, ob + HALF_F * 4u);   // odd rows
                tma_st_commit();                // wait deferred 2 stages
            }
        }
        if (l == 0) tma_st_wait0();
    }
}

// ---------------- host ----------------
extern "C" void kernel_launch(void* const* d_in, const int* in_sizes, int n_in,
                              void* d_out, int out_size)
{
    typedef CUresult (*EncFn)(CUtensorMap*, CUtensorMapDataType, cuuint32_t, void*,
                              const cuuint64_t*, const cuuint64_t*, const cuuint32_t*,
                              const cuuint32_t*, CUtensorMapInterleave, CUtensorMapSwizzle,
                              CUtensorMapL2promotion, CUtensorMapFloatOOBfill);
    void* h = dlopen("libcuda.so.1", RTLD_NOW | RTLD_GLOBAL);
    if (!h) h = dlopen("libcuda.so", RTLD_NOW | RTLD_GLOBAL);
    EncFn enc = (EncFn)dlsym(h, "cuTensorMapEncodeTiled");

    // packed row-pair view: [256 floats, 64*512 rows], pitch 1024B
    const cuuint64_t gdim[2]    = {256, 512ull * 64};
    const cuuint64_t gstride[1] = {1024};
    const cuuint32_t estr[2]    = {1, 1};
    const cuuint32_t box[2]     = {32, 64};              // 128B rows -> SW128

    CUtensorMap maps[5];
    for (int i = 0; i < 5; ++i) {
        enc(&maps[i], CU_TENSOR_MAP_DATA_TYPE_FLOAT32, 2, (void*)d_in[i],
            gdim, gstride, box, estr,
            CU_TENSOR_MAP_INTERLEAVE_NONE, CU_TENSOR_MAP_SWIZZLE_128B,
            CU_TENSOR_MAP_L2_PROMOTION_L2_128B, CU_TENSOR_MAP_FLOAT_OOB_FILL_NONE);
    }
    CUtensorMap mO;
    enc(&mO, CU_TENSOR_MAP_DATA_TYPE_FLOAT32, 2, d_out,
        gdim, gstride, box, estr,
        CU_TENSOR_MAP_INTERLEAVE_NONE, CU_TENSOR_MAP_SWIZZLE_128B,
        CU_TENSOR_MAP_L2_PROMOTION_L2_128B, CU_TENSOR_MAP_FLOAT_OOB_FILL_NONE);

    cudaFuncSetAttribute(gaterec2d_pk_kernel,
                         cudaFuncAttributeMaxDynamicSharedMemorySize, SMEM_BYTES);

    gaterec2d_pk_kernel<<<128, 64, SMEM_BYTES>>>(maps[0], maps[1], maps[2],
                                                 maps[3], maps[4], mO);
}